// round 15
// baseline (speedup 1.0000x reference)
#include <cuda_runtime.h>
#include <cuda_fp16.h>
#include <mma.h>
#include <math.h>

using namespace nvcuda;

#define N_NODES 20000
#define GM      20096       // nodes padded to 157*128 for guard-free wmma epilogue
#define N_EDGES 150000
#define FEAT    64
#define HEADS   8
#define N_RBF   20
#define CUTOFF  5.0f
#define NO      1024        // Q(512) + K(512) columns per node
#define NOUT    512         // per-table (HEADS*FEAT)
#define NBINS   4096
#define BINS_PER_BLK 64

// Scratch (device globals; no cudaMalloc allowed)
__device__ __half g_wth [FEAT * NO];                  // 128 KB : W transposed [f][o], fp16
__device__ float  g_wdkt[N_RBF * NOUT];               // 40 KB  : W_dk transposed [r][o]
__device__ __half g_qkh [(size_t)GM * NO];            // ~41 MB : per-node Q|K, fp16
__device__ __half g_dkh [(size_t)(NBINS + 1) * NOUT]; // ~4.2 MB : dk(dist) table, fp16

// ---------------------------------------------------------------------------
// Kernel A0: transpose W_dk [o][r] -> g_wdkt [r][o] (tiny, one-shot).
// ---------------------------------------------------------------------------
__global__ __launch_bounds__(256) void transpose_wdk(const float* __restrict__ W_dk)
{
    int idx = blockIdx.x * 256 + threadIdx.x;   // over N_RBF*NOUT = 10240
    if (idx >= N_RBF * NOUT) return;
    int r = idx / NOUT;
    int o = idx % NOUT;
    g_wdkt[idx] = W_dk[o * N_RBF + r];
}

// ---------------------------------------------------------------------------
// Kernel A: build dk table. 65 blocks x 512 threads (thread = o). Each thread
// keeps its 20 W_dk weights in REGISTERS (coalesced loads from g_wdkt, once
// per block) and loops over 64 bins; per bin only the 20-lane ef compute +
// 2 bars. Replaces the old per-bin stride-80B W_dk wavefront storm.
// ---------------------------------------------------------------------------
__global__ __launch_bounds__(512) void build_dk_table(const float* __restrict__ b_dk)
{
    __shared__ float ef[N_RBF];
    const int o = threadIdx.x;                  // 0..511
    float w[N_RBF];
#pragma unroll
    for (int r = 0; r < N_RBF; r++)
        w[r] = g_wdkt[r * NOUT + o];            // coalesced, L1-resident
    const float bias = b_dk[o];

    for (int bi = 0; bi < BINS_PER_BLK; bi++) {
        int row = blockIdx.x * BINS_PER_BLK + bi;
        if (row > NBINS) break;                 // uniform per block
        if (o < N_RBF) {
            float d = (float)row * (CUTOFF / (float)NBINS);
            if (row == 0) d = 1e-6f;            // row 0 never used (dist >= 0.5)
            float n = (float)(o + 1);
            float s = sinf(n * 3.14159265358979f * d / 5.0f) / d;
            float env = 0.5f * (cosf(3.14159265358979f * d / 5.0f) + 1.0f);
            if (d >= 5.0f) env = 0.0f;
            ef[o] = s * env;
        }
        __syncthreads();
        float z = bias;
#pragma unroll
        for (int r = 0; r < N_RBF; r++)
            z = fmaf(ef[r], w[r], z);
        float dk = z / (1.0f + expf(-z));       // silu
        g_dkh[(size_t)row * NOUT + o] = __float2half(dk);
        __syncthreads();                        // protect ef before next bin
    }
}

// ---------------------------------------------------------------------------
// Kernel A2: transpose W_q / W_k into k-major fp16 g_wth[f][o].
// ---------------------------------------------------------------------------
__global__ __launch_bounds__(256) void transpose_w(
    const float* __restrict__ W_q, const float* __restrict__ W_k)
{
    int idx = blockIdx.x * 256 + threadIdx.x;   // over FEAT*NO = 65536
    if (idx >= FEAT * NO) return;
    int f = idx / NO;
    int o = idx % NO;
    float v = (o < NOUT) ? W_q[o * FEAT + f] : W_k[(o - NOUT) * FEAT + f];
    g_wth[idx] = __float2half(v);
}

// ---------------------------------------------------------------------------
// Kernel B: smem-staged tensor-core GEMM (unchanged from the 105us pass).
//   g_qkh[n][o] = fp16( X[n][:] . Wt[:][o] + bias[o] )
// ---------------------------------------------------------------------------
#define TM 128
#define TN 128
#define ALD (FEAT + 8)      // 72
#define BLD (TN + 8)        // 136
__global__ __launch_bounds__(256) void qk_gemm_wmma(
    const float* __restrict__ x,
    const float* __restrict__ b_q, const float* __restrict__ b_k)
{
    __shared__ __align__(16) union SmU {
        struct {
            __half As[TM * ALD];                // 18432 B
            __half Bs[FEAT * BLD];              // 17408 B
        } ab;
        float Cs[64 * TN];                      // 32768 B
    } sm;                                       // 35840 B total
    __half* As = sm.ab.As;
    __half* Bs = sm.ab.Bs;
    float*  Cs = sm.Cs;

    const int tid = threadIdx.x;
    const int warp = tid >> 5;
    const int wm = warp >> 2;                   // 0..1 : 64-row half
    const int wn = warp & 3;                    // 0..3 : 32-col slice
    const int bm = blockIdx.x * TM;
    const int bn = blockIdx.y * TN;

#pragma unroll
    for (int p = 0; p < 8; p++) {
        int r = (tid >> 4) + p * 16;
        int c = tid & 15;                       // float4 column
        int node = bm + r;
        float4 v = make_float4(0.f, 0.f, 0.f, 0.f);
        if (node < N_NODES)
            v = *(const float4*)(x + (size_t)node * FEAT + c * 4);
        __half2* dst = (__half2*)&As[r * ALD + c * 4];
        dst[0] = __floats2half2_rn(v.x, v.y);
        dst[1] = __floats2half2_rn(v.z, v.w);
    }
#pragma unroll
    for (int p = 0; p < 4; p++) {
        int idx = tid + p * 256;
        int r = idx >> 4;
        int c = idx & 15;
        *(uint4*)&Bs[r * BLD + c * 8] =
            *(const uint4*)(g_wth + (size_t)r * NO + bn + c * 8);
    }
    __syncthreads();

    wmma::fragment<wmma::accumulator, 16, 16, 16, float> acc[4][2];
#pragma unroll
    for (int i = 0; i < 4; i++)
#pragma unroll
        for (int j = 0; j < 2; j++)
            wmma::fill_fragment(acc[i][j], 0.0f);

#pragma unroll
    for (int k = 0; k < FEAT; k += 16) {
        wmma::fragment<wmma::matrix_a, 16, 16, 16, __half, wmma::row_major> a[4];
        wmma::fragment<wmma::matrix_b, 16, 16, 16, __half, wmma::row_major> b[2];
#pragma unroll
        for (int i = 0; i < 4; i++)
            wmma::load_matrix_sync(a[i], &As[(wm * 64 + i * 16) * ALD + k], ALD);
#pragma unroll
        for (int j = 0; j < 2; j++)
            wmma::load_matrix_sync(b[j], &Bs[k * BLD + wn * 32 + j * 16], BLD);
#pragma unroll
        for (int i = 0; i < 4; i++)
#pragma unroll
            for (int j = 0; j < 2; j++)
                wmma::mma_sync(acc[i][j], a[i], b[j], acc[i][j]);
    }

#pragma unroll
    for (int hv = 0; hv < 2; hv++) {
        __syncthreads();                        // all mma reads of As/Bs done
        if (wm == hv) {
#pragma unroll
            for (int i = 0; i < 4; i++)
#pragma unroll
                for (int j = 0; j < 2; j++)
                    wmma::store_matrix_sync(&Cs[(i * 16) * TN + wn * 32 + j * 16],
                                            acc[i][j], TN, wmma::mem_row_major);
        }
        __syncthreads();
        for (int t = tid; t < 64 * 64; t += 256) {
            int r = t >> 6, c2 = t & 63;
            int o = bn + c2 * 2;                // even; NOUT even -> no straddle
            float bx = (o     < NOUT) ? b_q[o]     : b_k[o - NOUT];
            float by = (o + 1 < NOUT) ? b_q[o + 1] : b_k[o + 1 - NOUT];
            float2 cv = *(const float2*)&Cs[r * TN + c2 * 2];
            __half2 outv = __floats2half2_rn(cv.x + bx, cv.y + by);
            *((__half2*)(g_qkh + (size_t)(bm + hv * 64 + r) * NO + o)) = outv;
        }
    }
}

// ---------------------------------------------------------------------------
// Kernel C: one warp per edge, HALF2 math path (issue-bound fix: lerp and
// q*k*dk in HSUB2/HFMA2/HMUL2, single cvt of the product pair, fp32 accumulate).
// Lane l, chunk j in {0,1}: uint4 = halfs o = 256j + 8l..+7, head 4j+(l>>3).
// ---------------------------------------------------------------------------
__device__ __forceinline__ float dot8_h2(uint4 qu, uint4 ku, uint4 au, uint4 bu,
                                         __half2 fr2)
{
    const __half2* q2 = (const __half2*)&qu;
    const __half2* k2 = (const __half2*)&ku;
    const __half2* a2 = (const __half2*)&au;
    const __half2* b2 = (const __half2*)&bu;
    float s = 0.f;
#pragma unroll
    for (int i = 0; i < 4; i++) {
        __half2 dk = __hfma2(fr2, __hsub2(b2[i], a2[i]), a2[i]);  // lerp
        __half2 t  = __hmul2(__hmul2(q2[i], k2[i]), dk);          // q*k*dk
        float2 tf  = __half22float2(t);
        s += tf.x + tf.y;                                         // fp32 accum
    }
    return s;
}

__global__ __launch_bounds__(256) void edge_kernel(
    const float* __restrict__ dist, const int* __restrict__ nbrs,
    float* __restrict__ out)
{
    int warp = (blockIdx.x * blockDim.x + threadIdx.x) >> 5;
    int lane = threadIdx.x & 31;
    if (warp >= N_EDGES) return;
    const int e = warp;

    float d = dist[e];
    int ni = nbrs[2 * e];
    int nj = nbrs[2 * e + 1];

    float t = d * ((float)NBINS / CUTOFF);
    int b = (int)t;
    if (b < 0) b = 0;
    if (b > NBINS - 1) b = NBINS - 1;
    float fr = t - (float)b;
    __half2 fr2 = __half2half2(__float2half_rn(fr));

    const uint4* qp = (const uint4*)(g_qkh + (size_t)ni * NO);
    const uint4* kp = (const uint4*)(g_qkh + (size_t)nj * NO + NOUT);
    const uint4* d0 = (const uint4*)(g_dkh + (size_t)b * NOUT);
    const uint4* d1 = (const uint4*)(g_dkh + (size_t)(b + 1) * NOUT);

    uint4 q0 = qp[lane],      k0 = kp[lane];
    uint4 a0 = d0[lane],      b0 = d1[lane];
    uint4 q1 = qp[32 + lane], k1 = kp[32 + lane];
    uint4 a1 = d0[32 + lane], b1 = d1[32 + lane];

    float acc0 = dot8_h2(q0, k0, a0, b0, fr2);
    float acc1 = dot8_h2(q1, k1, a1, b1, fr2);

#pragma unroll
    for (int off = 4; off >= 1; off >>= 1) {
        acc0 += __shfl_xor_sync(0xffffffffu, acc0, off);
        acc1 += __shfl_xor_sync(0xffffffffu, acc1, off);
    }

    if ((lane & 7) == 0) {
        int g = lane >> 3;                      // 0..3
        out[(size_t)e * HEADS + g]     = acc0 / (1.0f + expf(-acc0));  // heads 0..3
        out[(size_t)e * HEADS + 4 + g] = acc1 / (1.0f + expf(-acc1));  // heads 4..7
    }
}

// ---------------------------------------------------------------------------
// Launch. Inputs (metadata order): dist, nbrs, x_i, W_q, b_q, W_k, b_k, W_dk, b_dk
// ---------------------------------------------------------------------------
extern "C" void kernel_launch(void* const* d_in, const int* in_sizes, int n_in,
                              void* d_out, int out_size)
{
    const float* dist = (const float*)d_in[0];
    const int*   nbrs = (const int*)  d_in[1];
    const float* x_i  = (const float*)d_in[2];
    const float* W_q  = (const float*)d_in[3];
    const float* b_q  = (const float*)d_in[4];
    const float* W_k  = (const float*)d_in[5];
    const float* b_k  = (const float*)d_in[6];
    const float* W_dk = (const float*)d_in[7];
    const float* b_dk = (const float*)d_in[8];
    float* out = (float*)d_out;

    transpose_wdk<<<(N_RBF * NOUT + 255) / 256, 256>>>(W_dk);
    build_dk_table<<<(NBINS + 1 + BINS_PER_BLK - 1) / BINS_PER_BLK, 512>>>(b_dk);
    transpose_w<<<(FEAT * NO + 255) / 256, 256>>>(W_q, W_k);
    qk_gemm_wmma<<<dim3(GM / TM, NO / TN), 256>>>(x_i, b_q, b_k);
    edge_kernel<<<(N_EDGES * 32 + 255) / 256, 256>>>(dist, nbrs, out);
}